// round 5
// baseline (speedup 1.0000x reference)
#include <cuda_runtime.h>
#include <math.h>

#define NN   50000
#define FF   128
#define EE1  400000
#define EE2  100000
#define EET  500000      // EE1 + EE2
#define LALPHA 0.2f
#define DDAMP  0.85f

// ---------------- scratch (static device arrays; no runtime allocation) ----------
__device__ float g_xa[(size_t)NN * 256];     // [N][256]: cols 0..127 = x@a1^T, 128..255 = x@a2^T
__device__ float g_em[(size_t)EET * 128];    // edge_m  [E][128]
__device__ float g_ee[EET];                  // edge_e
__device__ float g_att[EET];                 // rel_att
__device__ float g_arow[NN];
__device__ float g_erow[NN];
__device__ float g_ecol[NN];
__device__ float g_rank[NN];

__device__ __forceinline__ float lrelu(float x) { return x > 0.f ? x : LALPHA * x; }
__device__ __forceinline__ int   clampN(int v)  { return v < 0 ? 0 : (v >= NN ? NN - 1 : v); }

// Edge lists arrive as int32 (harness downcasts int64). e1: [2,EE1], e2: [2,EE2].
__device__ __forceinline__ void edge_sd(const int* __restrict__ e1, const int* __restrict__ e2,
                                        long long e, int& s, int& d) {
    if (e < EE1) { s = e1[e];        d = e1[EE1 + e]; }
    else         { long long q = e - EE1; s = e2[q]; d = e2[EE2 + q]; }
    s = clampN(s); d = clampN(d);
}

// ---------------- K0: zero accumulators + output h region --------------------------
__global__ void k_zero(float* __restrict__ out) {
    int i = blockIdx.x * blockDim.x + threadIdx.x;
    int stride = gridDim.x * blockDim.x;
    for (int n = i; n < NN; n += stride) { g_arow[n] = 0.f; g_erow[n] = 0.f; g_ecol[n] = 0.f; }
    for (size_t j = i; j < (size_t)NN * 128; j += stride) out[j] = 0.f;
}

// ---------------- K1: node GEMM  xa1 = x@a1^T, xa2 = x@a2^T ------------------------
// a is [128, 384] row-major.  a1 = a[:, 0:128], a2 = a[:, 128:256].
__global__ void k_node_gemm(const float* __restrict__ x, const float* __restrict__ a) {
    extern __shared__ float sm[];
    float* wT = sm;                  // 128*256
    float* xs = sm + 128 * 256;      // 32*128
    int t = threadIdx.x, lane = t & 31, w = t >> 5;

    for (int i = t; i < 128 * 256; i += 256) {
        int k = i >> 8, o = i & 255;
        wT[i] = (o < 128) ? a[o * 384 + k] : a[(o - 128) * 384 + 128 + k];
    }
    __syncthreads();

    int base = blockIdx.x * 32;
    for (int i = t; i < 32 * 128; i += 256) {
        int nn = base + (i >> 7);
        xs[i] = (nn < NN) ? x[(size_t)nn * 128 + (i & 127)] : 0.f;
    }
    __syncthreads();

    float acc[4][8];
#pragma unroll
    for (int j = 0; j < 4; j++)
#pragma unroll
        for (int q = 0; q < 8; q++) acc[j][q] = 0.f;

#pragma unroll 4
    for (int k = 0; k < 128; k++) {
        float4 w0 = *(float4*)&wT[k * 256 + 4 * lane];
        float4 w1 = *(float4*)&wT[k * 256 + 128 + 4 * lane];
#pragma unroll
        for (int j = 0; j < 4; j++) {
            float xv = xs[(4 * w + j) * 128 + k];
            acc[j][0] += xv * w0.x; acc[j][1] += xv * w0.y;
            acc[j][2] += xv * w0.z; acc[j][3] += xv * w0.w;
            acc[j][4] += xv * w1.x; acc[j][5] += xv * w1.y;
            acc[j][6] += xv * w1.z; acc[j][7] += xv * w1.w;
        }
    }
#pragma unroll
    for (int j = 0; j < 4; j++) {
        int n = base + 4 * w + j;
        if (n < NN) {
            float4 v0 = {acc[j][0], acc[j][1], acc[j][2], acc[j][3]};
            float4 v1 = {acc[j][4], acc[j][5], acc[j][6], acc[j][7]};
            *(float4*)&g_xa[(size_t)n * 256 + 4 * lane] = v0;
            *(float4*)&g_xa[(size_t)n * 256 + 128 + 4 * lane] = v1;
        }
    }
}

// ---------------- K2: edge GEMM z = xa1[src]+xa2[dst]+rel@a3^T, edge_m, edge_e -----
__global__ void k_edge_gemm(const float* __restrict__ emb1, const float* __restrict__ emb2,
                            const int* __restrict__ e1, const int* __restrict__ e2,
                            const float* __restrict__ a, const float* __restrict__ a2) {
    extern __shared__ float sm[];
    float* wT = sm;                 // 128*128
    float* rs = sm + 128 * 128;     // 32*128
    int t = threadIdx.x, lane = t & 31, w = t >> 5;

    for (int i = t; i < 128 * 128; i += 256) {
        int k = i >> 7, o = i & 127;
        wT[i] = a[o * 384 + 256 + k];
    }
    float4 a2v = *(const float4*)&a2[4 * lane];
    __syncthreads();

    const int NTILES = EET / 32;   // 15625 exactly
    for (int tile = blockIdx.x; tile < NTILES; tile += gridDim.x) {
        long long base = (long long)tile * 32;
        __syncthreads();
        for (int i = t; i < 32 * 128; i += 256) {
            long long e = base + (i >> 7);
            const float* src = (e < EE1) ? (emb1 + e * 128) : (emb2 + (e - EE1) * 128);
            rs[i] = src[i & 127];
        }
        __syncthreads();

        int didx[4];
        float acc[4][4];
#pragma unroll
        for (int j = 0; j < 4; j++) {
            long long e = base + 4 * w + j;
            int s, d;
            edge_sd(e1, e2, e, s, d);
            didx[j] = d;
            float4 v1 = *(const float4*)&g_xa[(size_t)s * 256 + 4 * lane];
            float4 v2 = *(const float4*)&g_xa[(size_t)d * 256 + 128 + 4 * lane];
            acc[j][0] = v1.x + v2.x; acc[j][1] = v1.y + v2.y;
            acc[j][2] = v1.z + v2.z; acc[j][3] = v1.w + v2.w;
        }

#pragma unroll 4
        for (int k = 0; k < 128; k++) {
            float4 wv = *(float4*)&wT[k * 128 + 4 * lane];
#pragma unroll
            for (int j = 0; j < 4; j++) {
                float rv = rs[(4 * w + j) * 128 + k];
                acc[j][0] += rv * wv.x; acc[j][1] += rv * wv.y;
                acc[j][2] += rv * wv.z; acc[j][3] += rv * wv.w;
            }
        }

        float dotp[4];
#pragma unroll
        for (int j = 0; j < 4; j++) {
            long long e = base + 4 * w + j;
            float4 m;
            m.x = lrelu(acc[j][0]); m.y = lrelu(acc[j][1]);
            m.z = lrelu(acc[j][2]); m.w = lrelu(acc[j][3]);
            *(float4*)&g_em[(size_t)e * 128 + 4 * lane] = m;
            dotp[j] = m.x * a2v.x + m.y * a2v.y + m.z * a2v.z + m.w * a2v.w;
        }
#pragma unroll
        for (int off = 16; off > 0; off >>= 1)
#pragma unroll
            for (int j = 0; j < 4; j++)
                dotp[j] += __shfl_xor_sync(0xFFFFFFFFu, dotp[j], off);

        if (lane < 4) {
            int j = lane;
            long long e = base + 4 * w + j;
            float ee = expf(-lrelu(dotp[j]));
            g_ee[e] = ee;
            atomicAdd(&g_arow[didx[j]], ee);
        }
    }
}

// ---------------- K3: rel_att = edge_e / a_rowsum[dst]; e_rowsum[src] += ----------
__global__ void k_att(const int* __restrict__ e1, const int* __restrict__ e2) {
    long long e = (long long)blockIdx.x * blockDim.x + threadIdx.x;
    if (e >= EET) return;
    int s, d;
    edge_sd(e1, e2, e, s, d);
    float denom = g_arow[d];
    if (denom == 0.f) denom = 1e-12f;
    float att = g_ee[e] / denom;
    g_att[e] = att;
    atomicAdd(&g_erow[s], att);
}

// ---------------- K4: val = att * rank[src] / e_rowsum[src]; e_colsum[dst] += ------
__global__ void k_val(const int* __restrict__ e1, const int* __restrict__ e2,
                      const float* __restrict__ rank_in) {
    long long e = (long long)blockIdx.x * blockDim.x + threadIdx.x;
    if (e >= EET) return;
    int s, d;
    edge_sd(e1, e2, e, s, d);
    float denom = g_erow[s];
    if (denom == 0.f) denom = 1e-12f;
    float val = g_att[e] * rank_in[s] / denom;
    atomicAdd(&g_ecol[d], val);
}

// ---------------- K5: new_rank --------------------------------------------------
__global__ void k_rank(float* __restrict__ out, int writeRank) {
    int n = blockIdx.x * blockDim.x + threadIdx.x;
    if (n >= NN) return;
    float nr = (1.0f - DDAMP) + DDAMP * g_ecol[n];
    g_rank[n] = nr;
    if (writeRank) out[(size_t)NN * 128 + n] = nr;
}

// ---------------- K6: h_prime scatter: out[dst] += (att*rank[src]) * edge_m -------
__global__ void k_scatter(const int* __restrict__ e1, const int* __restrict__ e2,
                          float* __restrict__ out) {
    long long gw = (long long)blockIdx.x * 8 + (threadIdx.x >> 5);  // one warp per edge
    int lane = threadIdx.x & 31;
    if (gw >= EET) return;
    long long e = gw;
    int s, d;
    edge_sd(e1, e2, e, s, d);
    float coeff = g_att[e] * g_rank[s];
    float4 m = *(const float4*)&g_em[(size_t)e * 128 + 4 * lane];
    float* o = out + (size_t)d * 128 + 4 * lane;
    atomicAdd(o + 0, coeff * m.x);
    atomicAdd(o + 1, coeff * m.y);
    atomicAdd(o + 2, coeff * m.z);
    atomicAdd(o + 3, coeff * m.w);
}

// ---------------- K7: elu in place ------------------------------------------------
__global__ void k_elu(float* __restrict__ out) {
    size_t i = (size_t)blockIdx.x * blockDim.x + threadIdx.x;
    if (i >= (size_t)NN * 128) return;
    float x = out[i];
    out[i] = x > 0.f ? x : expm1f(x);
}

// ---------------- launch ----------------------------------------------------------
// Inputs resolved BY ELEMENT COUNT (all eight unique), robust to metadata order:
//   input 6.4M f32 | edge 800K i32 | edge_embed 51.2M f32 | edge_list_nhop 200K i32
//   edge_embed_nhop 12.8M f32 | entity_rank 50K f32 | a 49152 f32 | a_2 128 f32
extern "C" void kernel_launch(void* const* d_in, const int* in_sizes, int n_in,
                              void* d_out, int out_size) {
    const float* x = 0;   const int* e1 = 0;  const float* emb1 = 0;
    const int*   e2 = 0;  const float* emb2 = 0; const float* rank_in = 0;
    const float* a = 0;   const float* a2 = 0;

    for (int i = 0; i < n_in; i++) {
        switch (in_sizes[i]) {
            case 6400000:  x       = (const float*)d_in[i]; break;
            case 800000:   e1      = (const int*)d_in[i];   break;
            case 51200000: emb1    = (const float*)d_in[i]; break;
            case 200000:   e2      = (const int*)d_in[i];   break;
            case 12800000: emb2    = (const float*)d_in[i]; break;
            case 50000:    rank_in = (const float*)d_in[i]; break;
            case 49152:    a       = (const float*)d_in[i]; break;
            case 128:      a2      = (const float*)d_in[i]; break;
            default: break;
        }
    }
    float* out = (float*)d_out;
    if (!x || !e1 || !emb1 || !e2 || !emb2 || !rank_in || !a || !a2) return;

    int writeRank = (out_size >= NN * 128 + NN) ? 1 : 0;

    size_t smemNode = (128 * 256 + 32 * 128) * sizeof(float);   // 147456
    size_t smemEdge = (128 * 128 + 32 * 128) * sizeof(float);   // 81920
    cudaFuncSetAttribute(k_node_gemm, cudaFuncAttributeMaxDynamicSharedMemorySize, (int)smemNode);
    cudaFuncSetAttribute(k_edge_gemm, cudaFuncAttributeMaxDynamicSharedMemorySize, (int)smemEdge);

    k_zero<<<512, 256>>>(out);
    k_node_gemm<<<(NN + 31) / 32, 256, smemNode>>>(x, a);
    k_edge_gemm<<<296, 256, smemEdge>>>(emb1, emb2, e1, e2, a, a2);
    k_att<<<(EET + 255) / 256, 256>>>(e1, e2);
    k_val<<<(EET + 255) / 256, 256>>>(e1, e2, rank_in);
    k_rank<<<(NN + 255) / 256, 256>>>(out, writeRank);
    k_scatter<<<(EET + 7) / 8, 256>>>(e1, e2, out);
    k_elu<<<(NN * 128 + 255) / 256, 256>>>(out);
}

// round 14
// speedup vs baseline: 1.0233x; 1.0233x over previous
#include <cuda_runtime.h>
#include <math.h>
#include <stdint.h>

#define NN   50000
#define FF   128
#define EE1  400000
#define EE2  100000
#define EET  500000      // EE1 + EE2
#define LALPHA 0.2f
#define DDAMP  0.85f
#define PADK 132         // smem row stride (words) for 128-wide tiles, conflict-free

// ---------------- scratch (static device arrays; no runtime allocation) ----------
__device__ float g_xa[(size_t)NN * 256];     // [N][256]: cols 0..127 = x@a1^T, 128..255 = x@a2^T
__device__ float g_em[(size_t)EET * 128];    // edge_m  [E][128]
__device__ float g_ee[EET];                  // edge_e
__device__ float g_att[EET];                 // rel_att
__device__ float g_arow[NN];
__device__ float g_erow[NN];
__device__ float g_ecol[NN];
__device__ float g_rank[NN];

__device__ __forceinline__ float lrelu(float x) { return x > 0.f ? x : LALPHA * x; }
__device__ __forceinline__ int   clampN(int v)  { return v < 0 ? 0 : (v >= NN ? NN - 1 : v); }

// Edge lists arrive as int32. e1: [2,EE1], e2: [2,EE2].
__device__ __forceinline__ void edge_sd(const int* __restrict__ e1, const int* __restrict__ e2,
                                        long long e, int& s, int& d) {
    if (e < EE1) { s = e1[e];        d = e1[EE1 + e]; }
    else         { long long q = e - EE1; s = e2[q]; d = e2[EE2 + q]; }
    s = clampN(s); d = clampN(d);
}

__device__ __forceinline__ float to_tf32(float x) {
    uint32_t u;
    asm("cvt.rna.tf32.f32 %0, %1;" : "=r"(u) : "f"(x));
    return __uint_as_float(u);
}

__device__ __forceinline__ void mma_tf32(float* c, const uint32_t* A, const uint32_t* B) {
    asm volatile(
        "mma.sync.aligned.m16n8k8.row.col.f32.tf32.tf32.f32 "
        "{%0,%1,%2,%3}, {%4,%5,%6,%7}, {%8,%9}, {%0,%1,%2,%3};\n"
        : "+f"(c[0]), "+f"(c[1]), "+f"(c[2]), "+f"(c[3])
        : "r"(A[0]), "r"(A[1]), "r"(A[2]), "r"(A[3]), "r"(B[0]), "r"(B[1]));
}

// ---------------- K0: zero accumulators + output h region --------------------------
__global__ void k_zero(float* __restrict__ out) {
    int i = blockIdx.x * blockDim.x + threadIdx.x;
    int stride = gridDim.x * blockDim.x;
    for (int n = i; n < NN; n += stride) { g_arow[n] = 0.f; g_erow[n] = 0.f; g_ecol[n] = 0.f; }
    for (size_t j = i; j < (size_t)NN * 128; j += stride) out[j] = 0.f;
}

// ---------------- K1: node GEMM  xa1 = x@a1^T, xa2 = x@a2^T (fp32 exact) ----------
__global__ void k_node_gemm(const float* __restrict__ x, const float* __restrict__ a) {
    extern __shared__ float sm[];
    float* wT = sm;                  // 128*256
    float* xs = sm + 128 * 256;      // 32*128
    int t = threadIdx.x, lane = t & 31, w = t >> 5;

    for (int i = t; i < 128 * 256; i += 256) {
        int k = i >> 8, o = i & 255;
        wT[i] = (o < 128) ? a[o * 384 + k] : a[(o - 128) * 384 + 128 + k];
    }
    __syncthreads();

    int base = blockIdx.x * 32;
    for (int i = t; i < 32 * 128; i += 256) {
        int nn = base + (i >> 7);
        xs[i] = (nn < NN) ? x[(size_t)nn * 128 + (i & 127)] : 0.f;
    }
    __syncthreads();

    float acc[4][8];
#pragma unroll
    for (int j = 0; j < 4; j++)
#pragma unroll
        for (int q = 0; q < 8; q++) acc[j][q] = 0.f;

#pragma unroll 4
    for (int k = 0; k < 128; k++) {
        float4 w0 = *(float4*)&wT[k * 256 + 4 * lane];
        float4 w1 = *(float4*)&wT[k * 256 + 128 + 4 * lane];
#pragma unroll
        for (int j = 0; j < 4; j++) {
            float xv = xs[(4 * w + j) * 128 + k];
            acc[j][0] += xv * w0.x; acc[j][1] += xv * w0.y;
            acc[j][2] += xv * w0.z; acc[j][3] += xv * w0.w;
            acc[j][4] += xv * w1.x; acc[j][5] += xv * w1.y;
            acc[j][6] += xv * w1.z; acc[j][7] += xv * w1.w;
        }
    }
#pragma unroll
    for (int j = 0; j < 4; j++) {
        int n = base + 4 * w + j;
        if (n < NN) {
            float4 v0 = {acc[j][0], acc[j][1], acc[j][2], acc[j][3]};
            float4 v1 = {acc[j][4], acc[j][5], acc[j][6], acc[j][7]};
            *(float4*)&g_xa[(size_t)n * 256 + 4 * lane] = v0;
            *(float4*)&g_xa[(size_t)n * 256 + 128 + 4 * lane] = v1;
        }
    }
}

// ---------------- K2: fused edge kernel (tf32 tensor-core GEMM + epilogue) --------
// Block: 256 thr (8 warps, 4x2 warp grid). Tile: 128 edges x 128 outputs (full N).
//   z = emb @ a3^T        (tf32 mma, fp32 accum)
//   z += xa1[src] + xa2[dst]   (fp32 bias gather, L2-resident)
//   m = lrelu(z) -> g_em; ee = exp(-lrelu(m . a2)) -> g_ee; atomic a_rowsum[dst]
__global__ void k_edge_tf32(const float* __restrict__ emb1, const float* __restrict__ emb2,
                            const int* __restrict__ e1, const int* __restrict__ e2,
                            const float* __restrict__ a, const float* __restrict__ a2) {
    extern __shared__ float sm[];
    float* Rs   = sm;                    // [128][PADK] edge-embed tile (tf32)
    float* Ws   = sm + 128 * PADK;       // [128][PADK] a3 rows (tf32): Ws[o][k]
    float* sdot = sm + 2 * 128 * PADK;   // [128] per-edge a2-dot accumulator
    int*   ssrc = (int*)(sdot + 128);    // [128]
    int*   sdst = ssrc + 128;            // [128]

    int t = threadIdx.x;
    int lane = t & 31, w = t >> 5;
    int wm = w & 3, wn = w >> 2;         // warp coords: 4 along M, 2 along N
    int gid = lane >> 2, tg = lane & 3;  // mma group row / thread-in-group

    long long base = (long long)blockIdx.x * 128;

    // ---- load W tile: Ws[o][k] = tf32(a[o*384 + 256 + k]) ----
    for (int i = t; i < 128 * 32; i += 256) {
        int o = i >> 5, c4 = (i & 31) << 2;
        float4 v = *(const float4*)&a[o * 384 + 256 + c4];
        float* p = &Ws[o * PADK + c4];
        p[0] = to_tf32(v.x); p[1] = to_tf32(v.y); p[2] = to_tf32(v.z); p[3] = to_tf32(v.w);
    }
    // ---- load R tile (edge embeddings), zero-pad past EET ----
    for (int i = t; i < 128 * 32; i += 256) {
        int r = i >> 5, c4 = (i & 31) << 2;
        long long e = base + r;
        float4 v = make_float4(0.f, 0.f, 0.f, 0.f);
        if (e < EET) {
            const float* src = (e < EE1) ? (emb1 + e * 128) : (emb2 + (e - EE1) * 128);
            v = *(const float4*)&src[c4];
        }
        float* p = &Rs[r * PADK + c4];
        p[0] = to_tf32(v.x); p[1] = to_tf32(v.y); p[2] = to_tf32(v.z); p[3] = to_tf32(v.w);
    }
    // ---- edge indices + dot accumulator init ----
    if (t < 128) {
        long long e = base + t;
        int s = 0, d = 0;
        if (e < EET) edge_sd(e1, e2, e, s, d);
        ssrc[t] = s; sdst[t] = d; sdot[t] = 0.f;
    }
    __syncthreads();

    // ---- mma mainloop: C[2 mt][8 nt][4] ----
    float c[2][8][4];
#pragma unroll
    for (int mt = 0; mt < 2; mt++)
#pragma unroll
        for (int nt = 0; nt < 8; nt++)
#pragma unroll
            for (int q = 0; q < 4; q++) c[mt][nt][q] = 0.f;

#pragma unroll
    for (int k0 = 0; k0 < 128; k0 += 8) {
        uint32_t af[2][4], bf[8][2];
#pragma unroll
        for (int mt = 0; mt < 2; mt++) {
            int row = wm * 32 + mt * 16 + gid;
            af[mt][0] = __float_as_uint(Rs[row * PADK + k0 + tg]);
            af[mt][1] = __float_as_uint(Rs[(row + 8) * PADK + k0 + tg]);
            af[mt][2] = __float_as_uint(Rs[row * PADK + k0 + tg + 4]);
            af[mt][3] = __float_as_uint(Rs[(row + 8) * PADK + k0 + tg + 4]);
        }
#pragma unroll
        for (int nt = 0; nt < 8; nt++) {
            int o = wn * 64 + nt * 8 + gid;
            bf[nt][0] = __float_as_uint(Ws[o * PADK + k0 + tg]);
            bf[nt][1] = __float_as_uint(Ws[o * PADK + k0 + tg + 4]);
        }
#pragma unroll
        for (int mt = 0; mt < 2; mt++)
#pragma unroll
            for (int nt = 0; nt < 8; nt++)
                mma_tf32(c[mt][nt], af[mt], bf[nt]);
    }

    // ---- epilogue: bias + lrelu + store edge_m + a2 dot ----
    float2 a2p[8];
#pragma unroll
    for (int nt = 0; nt < 8; nt++)
        a2p[nt] = *(const float2*)&a2[wn * 64 + nt * 8 + tg * 2];

    float dp[2][2] = {{0.f, 0.f}, {0.f, 0.f}};   // [mt][row-half]
#pragma unroll
    for (int mt = 0; mt < 2; mt++) {
        int r0 = wm * 32 + mt * 16 + gid;        // rows r0 (c0,c1) and r0+8 (c2,c3)
        int r1 = r0 + 8;
        long long eA = base + r0, eB = base + r1;
        int sA = ssrc[r0], dA = sdst[r0];
        int sB = ssrc[r1], dB = sdst[r1];
        const float* xaA1 = &g_xa[(size_t)sA * 256];
        const float* xaA2 = &g_xa[(size_t)dA * 256 + 128];
        const float* xaB1 = &g_xa[(size_t)sB * 256];
        const float* xaB2 = &g_xa[(size_t)dB * 256 + 128];
#pragma unroll
        for (int nt = 0; nt < 8; nt++) {
            int col = wn * 64 + nt * 8 + tg * 2;
            float2 b1A = *(const float2*)&xaA1[col];
            float2 b2A = *(const float2*)&xaA2[col];
            float2 b1B = *(const float2*)&xaB1[col];
            float2 b2B = *(const float2*)&xaB2[col];
            float m0 = lrelu(c[mt][nt][0] + b1A.x + b2A.x);
            float m1 = lrelu(c[mt][nt][1] + b1A.y + b2A.y);
            float m2 = lrelu(c[mt][nt][2] + b1B.x + b2B.x);
            float m3 = lrelu(c[mt][nt][3] + b1B.y + b2B.y);
            if (eA < EET) { float2 v = {m0, m1}; *(float2*)&g_em[(size_t)eA * 128 + col] = v; }
            if (eB < EET) { float2 v = {m2, m3}; *(float2*)&g_em[(size_t)eB * 128 + col] = v; }
            dp[mt][0] += m0 * a2p[nt].x + m1 * a2p[nt].y;
            dp[mt][1] += m2 * a2p[nt].x + m3 * a2p[nt].y;
        }
    }
    // reduce across the 4-thread quad that shares each row
#pragma unroll
    for (int off = 1; off <= 2; off <<= 1) {
        dp[0][0] += __shfl_xor_sync(0xFFFFFFFFu, dp[0][0], off);
        dp[0][1] += __shfl_xor_sync(0xFFFFFFFFu, dp[0][1], off);
        dp[1][0] += __shfl_xor_sync(0xFFFFFFFFu, dp[1][0], off);
        dp[1][1] += __shfl_xor_sync(0xFFFFFFFFu, dp[1][1], off);
    }
    if (tg == 0) {   // combine the 2 N-warps via smem atomics
        atomicAdd(&sdot[wm * 32 + gid],      dp[0][0]);
        atomicAdd(&sdot[wm * 32 + gid + 8],  dp[0][1]);
        atomicAdd(&sdot[wm * 32 + gid + 16], dp[1][0]);
        atomicAdd(&sdot[wm * 32 + gid + 24], dp[1][1]);
    }
    __syncthreads();

    if (t < 128) {
        long long e = base + t;
        if (e < EET) {
            float ee = expf(-lrelu(sdot[t]));
            g_ee[e] = ee;
            atomicAdd(&g_arow[sdst[t]], ee);
        }
    }
}

// ---------------- K3: rel_att = edge_e / a_rowsum[dst]; e_rowsum[src] += ----------
__global__ void k_att(const int* __restrict__ e1, const int* __restrict__ e2) {
    long long e = (long long)blockIdx.x * blockDim.x + threadIdx.x;
    if (e >= EET) return;
    int s, d;
    edge_sd(e1, e2, e, s, d);
    float denom = g_arow[d];
    if (denom == 0.f) denom = 1e-12f;
    float att = g_ee[e] / denom;
    g_att[e] = att;
    atomicAdd(&g_erow[s], att);
}

// ---------------- K4: val = att * rank[src] / e_rowsum[src]; e_colsum[dst] += ------
__global__ void k_val(const int* __restrict__ e1, const int* __restrict__ e2,
                      const float* __restrict__ rank_in) {
    long long e = (long long)blockIdx.x * blockDim.x + threadIdx.x;
    if (e >= EET) return;
    int s, d;
    edge_sd(e1, e2, e, s, d);
    float denom = g_erow[s];
    if (denom == 0.f) denom = 1e-12f;
    float val = g_att[e] * rank_in[s] / denom;
    atomicAdd(&g_ecol[d], val);
}

// ---------------- K5: new_rank --------------------------------------------------
__global__ void k_rank(float* __restrict__ out, int writeRank) {
    int n = blockIdx.x * blockDim.x + threadIdx.x;
    if (n >= NN) return;
    float nr = (1.0f - DDAMP) + DDAMP * g_ecol[n];
    g_rank[n] = nr;
    if (writeRank) out[(size_t)NN * 128 + n] = nr;
}

// ---------------- K6: h_prime scatter: out[dst] += (att*rank[src]) * edge_m -------
__global__ void k_scatter(const int* __restrict__ e1, const int* __restrict__ e2,
                          float* __restrict__ out) {
    long long gw = (long long)blockIdx.x * 8 + (threadIdx.x >> 5);  // one warp per edge
    int lane = threadIdx.x & 31;
    if (gw >= EET) return;
    long long e = gw;
    int s, d;
    edge_sd(e1, e2, e, s, d);
    float coeff = g_att[e] * g_rank[s];
    float4 m = *(const float4*)&g_em[(size_t)e * 128 + 4 * lane];
    float* o = out + (size_t)d * 128 + 4 * lane;
    atomicAdd(o + 0, coeff * m.x);
    atomicAdd(o + 1, coeff * m.y);
    atomicAdd(o + 2, coeff * m.z);
    atomicAdd(o + 3, coeff * m.w);
}

// ---------------- K7: elu in place ------------------------------------------------
__global__ void k_elu(float* __restrict__ out) {
    size_t i = (size_t)blockIdx.x * blockDim.x + threadIdx.x;
    if (i >= (size_t)NN * 128) return;
    float x = out[i];
    out[i] = x > 0.f ? x : expm1f(x);
}

// ---------------- launch ----------------------------------------------------------
// Inputs resolved BY ELEMENT COUNT (all eight unique), robust to metadata order.
extern "C" void kernel_launch(void* const* d_in, const int* in_sizes, int n_in,
                              void* d_out, int out_size) {
    const float* x = 0;   const int* e1 = 0;  const float* emb1 = 0;
    const int*   e2 = 0;  const float* emb2 = 0; const float* rank_in = 0;
    const float* a = 0;   const float* a2 = 0;

    for (int i = 0; i < n_in; i++) {
        switch (in_sizes[i]) {
            case 6400000:  x       = (const float*)d_in[i]; break;
            case 800000:   e1      = (const int*)d_in[i];   break;
            case 51200000: emb1    = (const float*)d_in[i]; break;
            case 200000:   e2      = (const int*)d_in[i];   break;
            case 12800000: emb2    = (const float*)d_in[i]; break;
            case 50000:    rank_in = (const float*)d_in[i]; break;
            case 49152:    a       = (const float*)d_in[i]; break;
            case 128:      a2      = (const float*)d_in[i]; break;
            default: break;
        }
    }
    float* out = (float*)d_out;
    if (!x || !e1 || !emb1 || !e2 || !emb2 || !rank_in || !a || !a2) return;

    int writeRank = (out_size >= NN * 128 + NN) ? 1 : 0;

    size_t smemNode = (128 * 256 + 32 * 128) * sizeof(float);             // 147456
    size_t smemEdge = (2 * 128 * PADK + 128) * sizeof(float) + 256 * 4;   // 136704
    cudaFuncSetAttribute(k_node_gemm, cudaFuncAttributeMaxDynamicSharedMemorySize, (int)smemNode);
    cudaFuncSetAttribute(k_edge_tf32, cudaFuncAttributeMaxDynamicSharedMemorySize, (int)smemEdge);

    k_zero<<<512, 256>>>(out);
    k_node_gemm<<<(NN + 31) / 32, 256, smemNode>>>(x, a);
    k_edge_tf32<<<(EET + 127) / 128, 256, smemEdge>>>(emb1, emb2, e1, e2, a, a2);
    k_att<<<(EET + 255) / 256, 256>>>(e1, e2);
    k_val<<<(EET + 255) / 256, 256>>>(e1, e2, rank_in);
    k_rank<<<(NN + 255) / 256, 256>>>(out, writeRank);
    k_scatter<<<(EET + 7) / 8, 256>>>(e1, e2, out);
    k_elu<<<(NN * 128 + 255) / 256, 256>>>(out);
}

// round 16
// speedup vs baseline: 1.0358x; 1.0122x over previous
#include <cuda_runtime.h>
#include <math.h>
#include <stdint.h>

#define NN   50000
#define FF   128
#define EE1  400000
#define EE2  100000
#define EET  500000      // EE1 + EE2
#define LALPHA 0.2f
#define DDAMP  0.85f
#define PADK 132         // smem row stride (words) for 128-wide tiles, conflict-free

// ---------------- scratch (static device arrays; no runtime allocation) ----------
__device__ float g_xa[(size_t)NN * 256];     // [N][256]: cols 0..127 = x@a1^T, 128..255 = x@a2^T
__device__ float g_em[(size_t)EET * 128];    // edge_m  [E][128]
__device__ float g_ee[EET];                  // edge_e
__device__ float g_att[EET];                 // rel_att
__device__ float g_arow[NN];
__device__ float g_erow[NN];
__device__ float g_ecol[NN];
__device__ float g_rank[NN];
// CSR by destination node
__device__ int   g_cnt[NN];
__device__ int   g_pos[NN];
__device__ int   g_off[NN + 1];
__device__ int   g_eidx[EET];

__device__ __forceinline__ float lrelu(float x) { return x > 0.f ? x : LALPHA * x; }
__device__ __forceinline__ int   clampN(int v)  { return v < 0 ? 0 : (v >= NN ? NN - 1 : v); }

// Edge lists arrive as int32. e1: [2,EE1], e2: [2,EE2].
__device__ __forceinline__ void edge_sd(const int* __restrict__ e1, const int* __restrict__ e2,
                                        long long e, int& s, int& d) {
    if (e < EE1) { s = e1[e];        d = e1[EE1 + e]; }
    else         { long long q = e - EE1; s = e2[q]; d = e2[EE2 + q]; }
    s = clampN(s); d = clampN(d);
}
__device__ __forceinline__ int edge_src(const int* __restrict__ e1, const int* __restrict__ e2,
                                        long long e) {
    int s = (e < EE1) ? e1[e] : e2[e - EE1];
    return clampN(s);
}

__device__ __forceinline__ float to_tf32(float x) {
    uint32_t u;
    asm("cvt.rna.tf32.f32 %0, %1;" : "=r"(u) : "f"(x));
    return __uint_as_float(u);
}

__device__ __forceinline__ void mma_tf32(float* c, const uint32_t* A, const uint32_t* B) {
    asm volatile(
        "mma.sync.aligned.m16n8k8.row.col.f32.tf32.tf32.f32 "
        "{%0,%1,%2,%3}, {%4,%5,%6,%7}, {%8,%9}, {%0,%1,%2,%3};\n"
        : "+f"(c[0]), "+f"(c[1]), "+f"(c[2]), "+f"(c[3])
        : "r"(A[0]), "r"(A[1]), "r"(A[2]), "r"(A[3]), "r"(B[0]), "r"(B[1]));
}

// ---------------- K0: zero accumulators + CSR counters -----------------------------
__global__ void k_zero() {
    int i = blockIdx.x * blockDim.x + threadIdx.x;
    int stride = gridDim.x * blockDim.x;
    for (int n = i; n < NN; n += stride) {
        g_arow[n] = 0.f; g_erow[n] = 0.f; g_ecol[n] = 0.f;
        g_cnt[n] = 0; g_pos[n] = 0;
    }
}

// ---------------- CSR build: histogram / scan / fill -------------------------------
__global__ void k_hist(const int* __restrict__ e1, const int* __restrict__ e2) {
    long long e = (long long)blockIdx.x * blockDim.x + threadIdx.x;
    if (e >= EET) return;
    int s, d; edge_sd(e1, e2, e, s, d);
    atomicAdd(&g_cnt[d], 1);
}

__global__ void k_scan() {   // single block, 1024 threads
    __shared__ int warp_sums[32];
    int t = threadIdx.x;
    const int CH = (NN + 1023) / 1024;   // 49
    int begin = t * CH;
    int end = begin + CH; if (end > NN) end = NN;
    if (begin > NN) begin = NN;
    int s = 0;
    for (int i = begin; i < end; i++) s += g_cnt[i];
    int lane = t & 31, wid = t >> 5;
    int v = s;
#pragma unroll
    for (int off = 1; off < 32; off <<= 1) {
        int u = __shfl_up_sync(0xFFFFFFFFu, v, off);
        if (lane >= off) v += u;
    }
    if (lane == 31) warp_sums[wid] = v;
    __syncthreads();
    if (wid == 0) {
        int w = warp_sums[lane];
#pragma unroll
        for (int off = 1; off < 32; off <<= 1) {
            int u = __shfl_up_sync(0xFFFFFFFFu, w, off);
            if (lane >= off) w += u;
        }
        warp_sums[lane] = w;
    }
    __syncthreads();
    int excl = v - s + (wid > 0 ? warp_sums[wid - 1] : 0);
    int run = excl;
    for (int i = begin; i < end; i++) { int c = g_cnt[i]; g_off[i] = run; run += c; }
    if (t == 1023) g_off[NN] = run;
}

__global__ void k_fill(const int* __restrict__ e1, const int* __restrict__ e2) {
    long long e = (long long)blockIdx.x * blockDim.x + threadIdx.x;
    if (e >= EET) return;
    int s, d; edge_sd(e1, e2, e, s, d);
    int p = atomicAdd(&g_pos[d], 1);
    g_eidx[g_off[d] + p] = (int)e;
}

// ---------------- K1: node GEMM  xa1 = x@a1^T, xa2 = x@a2^T (fp32 exact) ----------
__global__ void k_node_gemm(const float* __restrict__ x, const float* __restrict__ a) {
    extern __shared__ float sm[];
    float* wT = sm;                  // 128*256
    float* xs = sm + 128 * 256;      // 32*128
    int t = threadIdx.x, lane = t & 31, w = t >> 5;

    for (int i = t; i < 128 * 256; i += 256) {
        int k = i >> 8, o = i & 255;
        wT[i] = (o < 128) ? a[o * 384 + k] : a[(o - 128) * 384 + 128 + k];
    }
    __syncthreads();

    int base = blockIdx.x * 32;
    for (int i = t; i < 32 * 128; i += 256) {
        int nn = base + (i >> 7);
        xs[i] = (nn < NN) ? x[(size_t)nn * 128 + (i & 127)] : 0.f;
    }
    __syncthreads();

    float acc[4][8];
#pragma unroll
    for (int j = 0; j < 4; j++)
#pragma unroll
        for (int q = 0; q < 8; q++) acc[j][q] = 0.f;

#pragma unroll 4
    for (int k = 0; k < 128; k++) {
        float4 w0 = *(float4*)&wT[k * 256 + 4 * lane];
        float4 w1 = *(float4*)&wT[k * 256 + 128 + 4 * lane];
#pragma unroll
        for (int j = 0; j < 4; j++) {
            float xv = xs[(4 * w + j) * 128 + k];
            acc[j][0] += xv * w0.x; acc[j][1] += xv * w0.y;
            acc[j][2] += xv * w0.z; acc[j][3] += xv * w0.w;
            acc[j][4] += xv * w1.x; acc[j][5] += xv * w1.y;
            acc[j][6] += xv * w1.z; acc[j][7] += xv * w1.w;
        }
    }
#pragma unroll
    for (int j = 0; j < 4; j++) {
        int n = base + 4 * w + j;
        if (n < NN) {
            float4 v0 = {acc[j][0], acc[j][1], acc[j][2], acc[j][3]};
            float4 v1 = {acc[j][4], acc[j][5], acc[j][6], acc[j][7]};
            *(float4*)&g_xa[(size_t)n * 256 + 4 * lane] = v0;
            *(float4*)&g_xa[(size_t)n * 256 + 128 + 4 * lane] = v1;
        }
    }
}

// ---------------- K2: fused edge kernel (tf32 tensor-core GEMM + epilogue) --------
__global__ void k_edge_tf32(const float* __restrict__ emb1, const float* __restrict__ emb2,
                            const int* __restrict__ e1, const int* __restrict__ e2,
                            const float* __restrict__ a, const float* __restrict__ a2) {
    extern __shared__ float sm[];
    float* Rs   = sm;                    // [128][PADK]
    float* Ws   = sm + 128 * PADK;       // [128][PADK]
    float* sdot = sm + 2 * 128 * PADK;   // [128]
    int*   ssrc = (int*)(sdot + 128);    // [128]
    int*   sdst = ssrc + 128;            // [128]

    int t = threadIdx.x;
    int lane = t & 31, w = t >> 5;
    int wm = w & 3, wn = w >> 2;
    int gid = lane >> 2, tg = lane & 3;

    long long base = (long long)blockIdx.x * 128;

    for (int i = t; i < 128 * 32; i += 256) {
        int o = i >> 5, c4 = (i & 31) << 2;
        float4 v = *(const float4*)&a[o * 384 + 256 + c4];
        float* p = &Ws[o * PADK + c4];
        p[0] = to_tf32(v.x); p[1] = to_tf32(v.y); p[2] = to_tf32(v.z); p[3] = to_tf32(v.w);
    }
    for (int i = t; i < 128 * 32; i += 256) {
        int r = i >> 5, c4 = (i & 31) << 2;
        long long e = base + r;
        float4 v = make_float4(0.f, 0.f, 0.f, 0.f);
        if (e < EET) {
            const float* src = (e < EE1) ? (emb1 + e * 128) : (emb2 + (e - EE1) * 128);
            v = *(const float4*)&src[c4];
        }
        float* p = &Rs[r * PADK + c4];
        p[0] = to_tf32(v.x); p[1] = to_tf32(v.y); p[2] = to_tf32(v.z); p[3] = to_tf32(v.w);
    }
    if (t < 128) {
        long long e = base + t;
        int s = 0, d = 0;
        if (e < EET) edge_sd(e1, e2, e, s, d);
        ssrc[t] = s; sdst[t] = d; sdot[t] = 0.f;
    }
    __syncthreads();

    float c[2][8][4];
#pragma unroll
    for (int mt = 0; mt < 2; mt++)
#pragma unroll
        for (int nt = 0; nt < 8; nt++)
#pragma unroll
            for (int q = 0; q < 4; q++) c[mt][nt][q] = 0.f;

#pragma unroll
    for (int k0 = 0; k0 < 128; k0 += 8) {
        uint32_t af[2][4], bf[8][2];
#pragma unroll
        for (int mt = 0; mt < 2; mt++) {
            int row = wm * 32 + mt * 16 + gid;
            af[mt][0] = __float_as_uint(Rs[row * PADK + k0 + tg]);
            af[mt][1] = __float_as_uint(Rs[(row + 8) * PADK + k0 + tg]);
            af[mt][2] = __float_as_uint(Rs[row * PADK + k0 + tg + 4]);
            af[mt][3] = __float_as_uint(Rs[(row + 8) * PADK + k0 + tg + 4]);
        }
#pragma unroll
        for (int nt = 0; nt < 8; nt++) {
            int o = wn * 64 + nt * 8 + gid;
            bf[nt][0] = __float_as_uint(Ws[o * PADK + k0 + tg]);
            bf[nt][1] = __float_as_uint(Ws[o * PADK + k0 + tg + 4]);
        }
#pragma unroll
        for (int mt = 0; mt < 2; mt++)
#pragma unroll
            for (int nt = 0; nt < 8; nt++)
                mma_tf32(c[mt][nt], af[mt], bf[nt]);
    }

    float2 a2p[8];
#pragma unroll
    for (int nt = 0; nt < 8; nt++)
        a2p[nt] = *(const float2*)&a2[wn * 64 + nt * 8 + tg * 2];

    float dp[2][2] = {{0.f, 0.f}, {0.f, 0.f}};
#pragma unroll
    for (int mt = 0; mt < 2; mt++) {
        int r0 = wm * 32 + mt * 16 + gid;
        int r1 = r0 + 8;
        long long eA = base + r0, eB = base + r1;
        int sA = ssrc[r0], dA = sdst[r0];
        int sB = ssrc[r1], dB = sdst[r1];
        const float* xaA1 = &g_xa[(size_t)sA * 256];
        const float* xaA2 = &g_xa[(size_t)dA * 256 + 128];
        const float* xaB1 = &g_xa[(size_t)sB * 256];
        const float* xaB2 = &g_xa[(size_t)dB * 256 + 128];
#pragma unroll
        for (int nt = 0; nt < 8; nt++) {
            int col = wn * 64 + nt * 8 + tg * 2;
            float2 b1A = *(const float2*)&xaA1[col];
            float2 b2A = *(const float2*)&xaA2[col];
            float2 b1B = *(const float2*)&xaB1[col];
            float2 b2B = *(const float2*)&xaB2[col];
            float m0 = lrelu(c[mt][nt][0] + b1A.x + b2A.x);
            float m1 = lrelu(c[mt][nt][1] + b1A.y + b2A.y);
            float m2 = lrelu(c[mt][nt][2] + b1B.x + b2B.x);
            float m3 = lrelu(c[mt][nt][3] + b1B.y + b2B.y);
            if (eA < EET) { float2 v = {m0, m1}; *(float2*)&g_em[(size_t)eA * 128 + col] = v; }
            if (eB < EET) { float2 v = {m2, m3}; *(float2*)&g_em[(size_t)eB * 128 + col] = v; }
            dp[mt][0] += m0 * a2p[nt].x + m1 * a2p[nt].y;
            dp[mt][1] += m2 * a2p[nt].x + m3 * a2p[nt].y;
        }
    }
#pragma unroll
    for (int off = 1; off <= 2; off <<= 1) {
        dp[0][0] += __shfl_xor_sync(0xFFFFFFFFu, dp[0][0], off);
        dp[0][1] += __shfl_xor_sync(0xFFFFFFFFu, dp[0][1], off);
        dp[1][0] += __shfl_xor_sync(0xFFFFFFFFu, dp[1][0], off);
        dp[1][1] += __shfl_xor_sync(0xFFFFFFFFu, dp[1][1], off);
    }
    if (tg == 0) {
        atomicAdd(&sdot[wm * 32 + gid],      dp[0][0]);
        atomicAdd(&sdot[wm * 32 + gid + 8],  dp[0][1]);
        atomicAdd(&sdot[wm * 32 + gid + 16], dp[1][0]);
        atomicAdd(&sdot[wm * 32 + gid + 24], dp[1][1]);
    }
    __syncthreads();

    if (t < 128) {
        long long e = base + t;
        if (e < EET) {
            float ee = expf(-lrelu(sdot[t]));
            g_ee[e] = ee;
            atomicAdd(&g_arow[sdst[t]], ee);
        }
    }
}

// ---------------- K3: rel_att = edge_e / a_rowsum[dst]; e_rowsum[src] += ----------
__global__ void k_att(const int* __restrict__ e1, const int* __restrict__ e2) {
    long long e = (long long)blockIdx.x * blockDim.x + threadIdx.x;
    if (e >= EET) return;
    int s, d;
    edge_sd(e1, e2, e, s, d);
    float denom = g_arow[d];
    if (denom == 0.f) denom = 1e-12f;
    float att = g_ee[e] / denom;
    g_att[e] = att;
    atomicAdd(&g_erow[s], att);
}

// ---------------- K4: val = att * rank[src] / e_rowsum[src]; e_colsum[dst] += ------
__global__ void k_val(const int* __restrict__ e1, const int* __restrict__ e2,
                      const float* __restrict__ rank_in) {
    long long e = (long long)blockIdx.x * blockDim.x + threadIdx.x;
    if (e >= EET) return;
    int s, d;
    edge_sd(e1, e2, e, s, d);
    float denom = g_erow[s];
    if (denom == 0.f) denom = 1e-12f;
    float val = g_att[e] * rank_in[s] / denom;
    atomicAdd(&g_ecol[d], val);
}

// ---------------- K5: new_rank ------------------------------------------------------
__global__ void k_rank(float* __restrict__ out, int writeRank) {
    int n = blockIdx.x * blockDim.x + threadIdx.x;
    if (n >= NN) return;
    float nr = (1.0f - DDAMP) + DDAMP * g_ecol[n];
    g_rank[n] = nr;
    if (writeRank) out[(size_t)NN * 128 + n] = nr;
}

// ---------------- K6: CSR scatter (NO output atomics) + fused ELU ------------------
// One block of 128 threads per destination node; thread t owns output column t.
__global__ void k_scatter_csr(const int* __restrict__ e1, const int* __restrict__ e2,
                              float* __restrict__ out) {
    int d = blockIdx.x;
    int t = threadIdx.x;
    int start = g_off[d], end = g_off[d + 1];
    float acc = 0.f;
    for (int i = start; i < end; i++) {
        int e = g_eidx[i];
        int s = edge_src(e1, e2, e);                 // broadcast LDG
        float coeff = g_att[e] * g_rank[s];          // broadcast LDGs
        acc += coeff * g_em[(size_t)e * 128 + t];    // coalesced 512B row read
    }
    out[(size_t)d * 128 + t] = acc > 0.f ? acc : expm1f(acc);
}

// ---------------- launch ----------------------------------------------------------
// Inputs resolved BY ELEMENT COUNT (all eight unique), robust to metadata order.
extern "C" void kernel_launch(void* const* d_in, const int* in_sizes, int n_in,
                              void* d_out, int out_size) {
    const float* x = 0;   const int* e1 = 0;  const float* emb1 = 0;
    const int*   e2 = 0;  const float* emb2 = 0; const float* rank_in = 0;
    const float* a = 0;   const float* a2 = 0;

    for (int i = 0; i < n_in; i++) {
        switch (in_sizes[i]) {
            case 6400000:  x       = (const float*)d_in[i]; break;
            case 800000:   e1      = (const int*)d_in[i];   break;
            case 51200000: emb1    = (const float*)d_in[i]; break;
            case 200000:   e2      = (const int*)d_in[i];   break;
            case 12800000: emb2    = (const float*)d_in[i]; break;
            case 50000:    rank_in = (const float*)d_in[i]; break;
            case 49152:    a       = (const float*)d_in[i]; break;
            case 128:      a2      = (const float*)d_in[i]; break;
            default: break;
        }
    }
    float* out = (float*)d_out;
    if (!x || !e1 || !emb1 || !e2 || !emb2 || !rank_in || !a || !a2) return;

    int writeRank = (out_size >= NN * 128 + NN) ? 1 : 0;

    size_t smemNode = (128 * 256 + 32 * 128) * sizeof(float);             // 147456
    size_t smemEdge = (2 * 128 * PADK + 128) * sizeof(float) + 256 * 4;   // 136704
    cudaFuncSetAttribute(k_node_gemm, cudaFuncAttributeMaxDynamicSharedMemorySize, (int)smemNode);
    cudaFuncSetAttribute(k_edge_tf32, cudaFuncAttributeMaxDynamicSharedMemorySize, (int)smemEdge);

    k_zero<<<256, 256>>>();
    k_hist<<<(EET + 255) / 256, 256>>>(e1, e2);
    k_scan<<<1, 1024>>>();
    k_fill<<<(EET + 255) / 256, 256>>>(e1, e2);
    k_node_gemm<<<(NN + 31) / 32, 256, smemNode>>>(x, a);
    k_edge_tf32<<<(EET + 127) / 128, 256, smemEdge>>>(emb1, emb2, e1, e2, a, a2);
    k_att<<<(EET + 255) / 256, 256>>>(e1, e2);
    k_val<<<(EET + 255) / 256, 256>>>(e1, e2, rank_in);
    k_rank<<<(NN + 255) / 256, 256>>>(out, writeRank);
    k_scatter_csr<<<NN, 128>>>(e1, e2, out);
}